// round 14
// baseline (speedup 1.0000x reference)
#include <cuda_runtime.h>
#include <math.h>

// Shape fixed by reference: B=2, L=2048, H=16, E=64
#define B_  2
#define L_  2048
#define H_  16
#define E_  64
#define BH_ 32            // B*H chains
#define CH_ 64            // chunk length along s
#define NC_ 32            // chunks per chain
#define HE_ 1024          // H*E row stride in floats
#define NBLK (BH_ * NC_)  // 1024 blocks
#define NOCT 8            // octs per chunk (8 rows each)

// Scratch (__device__ globals; no allocations allowed)
__device__ float2   g_agg [NBLK * 32];  // per-chunk sum of e*V (64 ch as float2)
__device__ float    g_aggE[NBLK];       // per-chunk sum of e
__device__ int      g_flag[NBLK];       // publish flags
__device__ unsigned g_ticket;           // scheduling-order ticket

__global__ void reset_all() {
    g_flag[threadIdx.x] = 0;
    if (threadIdx.x == 0) g_ticket = 0u;
}

__global__ __launch_bounds__(256, 6) void fused_scan_attn(
    const float* __restrict__ keys,
    const float* __restrict__ values,
    const float* __restrict__ w_score,
    float* __restrict__ out)
{
    __shared__ float  sV[CH_ * E_];      // 16 KB V tile (row-major)
    __shared__ float  se[CH_];           // e-scores
    __shared__ float2 spEV[NOCT * 32];   // per-oct EV partials [o][d2]
    __shared__ float  spE8[NOCT];        // per-oct E partials
    __shared__ float2 sq[NOCT * 32];     // cross-chunk prefix partials [o][d2]
    __shared__ float  srcp[CH_];         // 1 / cumulative-E per row
    __shared__ unsigned sTicket;

    const int tid = threadIdx.x;

    // ---- ticket: assign (bh, c) in scheduling order (chunk 0 first)
    if (tid == 0) sTicket = atomicAdd(&g_ticket, 1u);
    __syncthreads();
    const int vbid = (int)sTicket;
    const int c  = vbid >> 5;           // chunk 0..31 (monotone in ticket)
    const int bh = vbid & 31;           // chain
    const int b  = bh >> 4;
    const int h  = bh & 15;
    const int base = ((b * L_ + c * CH_) * H_ + h) * E_;

    const int d2 = tid & 31;            // channel pair (2*d2, 2*d2+1)
    const int o  = tid >> 5;            // oct 0..7 (rows 8o..8o+7)
    const int r0 = o * 8;

    // ---- phase 1: e[row] = exp(0.125 * dot(K[row], w_k)); 4 threads/row
    {
        const int row = tid >> 2, q = tid & 3;
        const float4* kq = reinterpret_cast<const float4*>(
            keys + base + row * HE_ + q * 16);
        const float4* wq = reinterpret_cast<const float4*>(
            w_score + E_ + q * 16);
        float dot = 0.f;
        #pragma unroll
        for (int j = 0; j < 4; j++) {
            const float4 k4 = kq[j];
            const float4 w4 = wq[j];
            dot += k4.x * w4.x + k4.y * w4.y + k4.z * w4.z + k4.w * w4.w;
        }
        dot += __shfl_xor_sync(0xffffffffu, dot, 1);
        dot += __shfl_xor_sync(0xffffffffu, dot, 2);
        if (q == 0) se[row] = __expf(dot * 0.125f);
    }

    // ---- phase 2: stage V tile into smem (float4, coalesced)
    {
        const float4* vg = reinterpret_cast<const float4*>(values + base);
        float4* sv4 = reinterpret_cast<float4*>(sV);
        #pragma unroll
        for (int i = 0; i < 4; i++) {
            const int idx = tid + i * 256;
            sv4[idx] = vg[(idx >> 4) * (HE_ / 4) + (idx & 15)];
        }
    }
    __syncthreads();

    // ---- phase 3: per-oct partials over 8 rows (float2 channels)
    {
        const float2* sv2 = reinterpret_cast<const float2*>(sV);
        float2 sEV = make_float2(0.f, 0.f);
        float  sumE = 0.f;
        #pragma unroll
        for (int r = 0; r < 8; r++) {
            const float e = se[r0 + r];
            const float2 v = sv2[(r0 + r) * 32 + d2];
            sumE += e;
            sEV.x = fmaf(e, v.x, sEV.x);
            sEV.y = fmaf(e, v.y, sEV.y);
        }
        spEV[o * 32 + d2] = sEV;
        if (d2 == 0) spE8[o] = sumE;
    }
    __syncthreads();

    // ---- publish block aggregate (R2-proven mechanics)
    if (tid < 32) {
        float2 a = make_float2(0.f, 0.f);
        #pragma unroll
        for (int s = 0; s < NOCT; s++) {
            const float2 t = spEV[s * 32 + tid];
            a.x += t.x; a.y += t.y;
        }
        g_agg[(bh * NC_ + c) * 32 + tid] = a;
        if (tid == 0) {
            float ae = 0.f;
            #pragma unroll
            for (int s = 0; s < NOCT; s++) ae += spE8[s];
            g_aggE[bh * NC_ + c] = ae;
        }
        __threadfence();                 // order agg stores before flag
    }
    __syncthreads();
    if (tid == 0) atomicExch(&g_flag[bh * NC_ + c], 1);

    // ---- lookback: wait for ALL predecessors (<=31); ticket order ensures
    //      predecessors were scheduled earlier -> deadlock-free w/o full
    //      co-residency.
    if (tid < c) {
        while (atomicAdd(&g_flag[bh * NC_ + tid], 0) == 0) { }
        __threadfence();                 // acquire predecessors' agg stores
    }
    __syncthreads();

    // ---- phase 4a: cross-chunk prefix partials (t ≡ o mod 8, t < c)
    {
        float2 p = make_float2(0.f, 0.f);
        for (int t = o; t < c; t += NOCT) {
            const float2 a = g_agg[(bh * NC_ + t) * 32 + d2];
            p.x += a.x; p.y += a.y;
        }
        sq[o * 32 + d2] = p;
    }

    // ---- warp 7: E-side. preE reduce + pair-scan + 2 reciprocals
    if (tid >= 224) {
        const int lane = tid & 31;
        float pe = (lane < c) ? g_aggE[bh * NC_ + lane] : 0.f;
        #pragma unroll
        for (int off = 16; off; off >>= 1)
            pe += __shfl_xor_sync(0xffffffffu, pe, off);
        const float ex = se[2 * lane];
        const float ey = se[2 * lane + 1];
        const float p = ex + ey;
        float incl = p;
        #pragma unroll
        for (int off = 1; off < 32; off <<= 1) {
            const float t = __shfl_up_sync(0xffffffffu, incl, off);
            if (lane >= off) incl += t;
        }
        const float excl = incl - p;
        srcp[2 * lane]     = __fdividef(1.f, pe + excl + ex);
        srcp[2 * lane + 1] = __fdividef(1.f, pe + incl);
    }
    __syncthreads();

    // ---- phase 4b: exclusive start + 8-row inclusive scan + float2 stores
    {
        float2 acc = make_float2(0.f, 0.f);
        #pragma unroll
        for (int s = 0; s < NOCT; s++) {
            const float2 t = sq[s * 32 + d2];
            acc.x += t.x; acc.y += t.y;
        }
        #pragma unroll
        for (int s = 0; s < NOCT - 1; s++) {
            if (s < o) {
                const float2 t = spEV[s * 32 + d2];
                acc.x += t.x; acc.y += t.y;
            }
        }
        const float2* sv2 = reinterpret_cast<const float2*>(sV);
        float2* o2 = reinterpret_cast<float2*>(out + base);
        #pragma unroll
        for (int j = 0; j < 8; j++) {
            const float e = se[r0 + j];
            const float2 v = sv2[(r0 + j) * 32 + d2];
            acc.x = fmaf(e, v.x, acc.x);
            acc.y = fmaf(e, v.y, acc.y);
            const float rc = srcp[r0 + j];
            float2 res;
            res.x = acc.x * rc;
            res.y = acc.y * rc;
            o2[(r0 + j) * (HE_ / 2) + d2] = res;
        }
    }
}

extern "C" void kernel_launch(void* const* d_in, const int* in_sizes, int n_in,
                              void* d_out, int out_size) {
    // inputs: 0=queries (unused: a_q cancels in softmax), 1=keys, 2=values,
    //         3=w_score, 4=b_score (unused: cancels)
    const float* keys   = (const float*)d_in[1];
    const float* values = (const float*)d_in[2];
    const float* w      = (const float*)d_in[3];
    float* out = (float*)d_out;

    reset_all<<<1, NBLK>>>();
    fused_scan_attn<<<NBLK, 256>>>(keys, values, w, out);
}

// round 16
// speedup vs baseline: 1.2937x; 1.2937x over previous
#include <cuda_runtime.h>
#include <math.h>

// Shape fixed by reference: B=2, L=2048, H=16, E=64
#define B_  2
#define L_  2048
#define H_  16
#define E_  64
#define BH_ 32            // B*H chains
#define CH_ 64            // chunk length along s
#define NC_ 32            // chunks per chain
#define HE_ 1024          // H*E row stride in floats
#define NBLK (BH_ * NC_)  // 1024 blocks
#define NSUB 4            // sub-groups of 64 channels
#define RPS  16           // rows per sub

// Scratch (__device__ globals; no allocations allowed)
__device__ float g_E   [BH_ * L_];           // e-scores
__device__ float g_agg [NBLK * E_];          // per-chunk sum of e*V
__device__ float g_aggE[NBLK];               // per-chunk sum of e
__device__ float g_sub [NBLK * NSUB * E_];   // per-sub partial sums of e*V

// ---------------- K1: e-scores + per-chunk/per-sub aggregates (R8 proven) --
__global__ __launch_bounds__(256, 8) void k_aggregate(
    const float* __restrict__ keys,
    const float* __restrict__ values,
    const float* __restrict__ w_score)
{
    __shared__ float sV[CH_ * E_];     // 16 KB V tile
    __shared__ float se[CH_];
    __shared__ float spEV[NSUB * E_];
    __shared__ float spE[NSUB];

    const int tid = threadIdx.x;
    const int blk = blockIdx.x;
    const int bh  = blk >> 5;          // / NC_
    const int c   = blk & 31;          // % NC_
    const int b   = bh >> 4;
    const int h   = bh & 15;
    const int base = ((b * L_ + c * CH_) * H_ + h) * E_;

    const int d   = tid & 63;
    const int sub = tid >> 6;
    const int r0  = sub * RPS;

    // e[row] = exp(0.125 * dot(K[row], w_k)); 4 threads per row
    {
        const int row = tid >> 2, q = tid & 3;
        const float4* kq = reinterpret_cast<const float4*>(
            keys + base + row * HE_ + q * 16);
        const float4* wq = reinterpret_cast<const float4*>(
            w_score + E_ + q * 16);
        float dot = 0.f;
        #pragma unroll
        for (int j = 0; j < 4; j++) {
            const float4 k4 = kq[j];
            const float4 w4 = wq[j];
            dot += k4.x * w4.x + k4.y * w4.y + k4.z * w4.z + k4.w * w4.w;
        }
        dot += __shfl_xor_sync(0xffffffffu, dot, 1);
        dot += __shfl_xor_sync(0xffffffffu, dot, 2);
        if (q == 0) {
            const float e = __expf(dot * 0.125f);
            se[row] = e;
            g_E[bh * L_ + c * CH_ + row] = e;
        }
    }

    // stage V tile (float4, coalesced)
    {
        const float4* vg = reinterpret_cast<const float4*>(values + base);
        float4* sv4 = reinterpret_cast<float4*>(sV);
        #pragma unroll
        for (int i = 0; i < 4; i++) {
            const int idx = tid + i * 256;
            sv4[idx] = vg[(idx >> 4) * (HE_ / 4) + (idx & 15)];
        }
    }
    __syncthreads();

    // per-sub partial aggregates over 16 rows; persist per-sub EV partials
    {
        float sumE = 0.f, sumEV = 0.f;
        #pragma unroll
        for (int r = 0; r < RPS; r++) {
            const float e = se[r0 + r];
            sumE += e;
            sumEV = fmaf(e, sV[(r0 + r) * E_ + d], sumEV);
        }
        g_sub[(blk * NSUB + sub) * E_ + d] = sumEV;
        spEV[sub * E_ + d] = sumEV;
        if (d == 0) spE[sub] = sumE;
    }
    __syncthreads();

    if (tid < E_) {
        g_agg[blk * E_ + tid] =
            spEV[tid] + spEV[E_ + tid] + spEV[2 * E_ + tid] + spEV[3 * E_ + tid];
        if (tid == 0)
            g_aggE[blk] = spE[0] + spE[1] + spE[2] + spE[3];
    }

#if __CUDA_ARCH__ >= 900
    // signal PDL: this block's work is issued; secondary may begin scheduling
    cudaTriggerProgrammaticLaunchCompletion();
#endif
}

// ---------------- K2: PDL secondary — V prologue overlaps K1 tail ----------
__global__ __launch_bounds__(256, 8) void k_output(
    const float* __restrict__ values,
    float* __restrict__ out)
{
    __shared__ float sV[CH_ * E_];     // 16 KB V tile (prologue-staged)
    __shared__ float se[CH_];          // e-scores for this chunk
    __shared__ float srcp[CH_];        // 1 / cumulative-E per row
    __shared__ float sqEV[NSUB * E_];  // chunk-prefix partials

    const int tid = threadIdx.x;
    const int blk = blockIdx.x;
    const int bh  = blk >> 5;
    const int c   = blk & 31;
    const int b   = bh >> 4;
    const int h   = bh & 15;
    const int base = ((b * L_ + c * CH_) * H_ + h) * E_;

    const int d   = tid & 63;
    const int sub = tid >> 6;
    const int r0  = sub * RPS;

    // ---- prologue (independent of K1): stage V tile into smem
    {
        const float4* vg = reinterpret_cast<const float4*>(values + base);
        float4* sv4 = reinterpret_cast<float4*>(sV);
        #pragma unroll
        for (int i = 0; i < 4; i++) {
            const int idx = tid + i * 256;
            sv4[idx] = vg[(idx >> 4) * (HE_ / 4) + (idx & 15)];
        }
    }

#if __CUDA_ARCH__ >= 900
    // wait for K1's writes (g_E / g_agg / g_aggE / g_sub) to be visible
    cudaGridDependencySynchronize();
#endif

    // ---- chunk-prefix EV loads, split NSUB ways
    {
        float pEV = 0.f;
        for (int t = sub; t < c; t += NSUB)
            pEV += g_agg[(bh * NC_ + t) * E_ + d];
        sqEV[sub * E_ + d] = pEV;
    }

    // ---- warp 7: E-side. preE reduce + pair-scan + reciprocals (2 MUFU)
    if (tid >= 224) {
        const int lane = tid & 31;
        float pe = (lane < c) ? g_aggE[bh * NC_ + lane] : 0.f;
        #pragma unroll
        for (int o = 16; o; o >>= 1) pe += __shfl_xor_sync(0xffffffffu, pe, o);
        const float2 e2 = reinterpret_cast<const float2*>(
            g_E + bh * L_ + c * CH_)[lane];
        const float p = e2.x + e2.y;
        float incl = p;
        #pragma unroll
        for (int o = 1; o < 32; o <<= 1) {
            const float t = __shfl_up_sync(0xffffffffu, incl, o);
            if (lane >= o) incl += t;
        }
        const float excl = incl - p;
        se[2 * lane]     = e2.x;
        se[2 * lane + 1] = e2.y;
        srcp[2 * lane]     = __fdividef(1.f, pe + excl + e2.x);
        srcp[2 * lane + 1] = __fdividef(1.f, pe + incl);
    }
    __syncthreads();

    // ---- exclusive EV start for this thread
    float accEV = sqEV[d] + sqEV[E_ + d] + sqEV[2 * E_ + d] + sqEV[3 * E_ + d];
    #pragma unroll
    for (int s = 0; s < NSUB - 1; s++)
        if (s < sub) accEV += g_sub[(blk * NSUB + s) * E_ + d];

    // ---- inclusive scan over 16 rows, V from smem, divide-free output
    float* o = out + base + r0 * HE_ + d;
    #pragma unroll
    for (int r = 0; r < RPS; r++) {
        accEV = fmaf(se[r0 + r], sV[(r0 + r) * E_ + d], accEV);
        o[r * HE_] = accEV * srcp[r0 + r];
    }
}

extern "C" void kernel_launch(void* const* d_in, const int* in_sizes, int n_in,
                              void* d_out, int out_size) {
    // inputs: 0=queries (unused: a_q cancels in softmax), 1=keys, 2=values,
    //         3=w_score, 4=b_score (unused: cancels)
    const float* keys   = (const float*)d_in[1];
    const float* values = (const float*)d_in[2];
    const float* w      = (const float*)d_in[3];
    float* out = (float*)d_out;

    k_aggregate<<<NBLK, 256>>>(keys, values, w);

    // K2 as a PDL secondary on the same (capture) stream — no streams/events,
    // no allocations; the dependency is expressed via the launch attribute.
    cudaLaunchConfig_t cfg = {};
    cfg.gridDim = dim3(NBLK, 1, 1);
    cfg.blockDim = dim3(256, 1, 1);
    cfg.dynamicSmemBytes = 0;
    cfg.stream = 0;
    cudaLaunchAttribute attr[1];
    attr[0].id = cudaLaunchAttributeProgrammaticStreamSerialization;
    attr[0].val.programmaticStreamSerializationAllowed = 1;
    cfg.attrs = attr;
    cfg.numAttrs = 1;
    cudaLaunchKernelEx(&cfg, k_output, values, out);
}

// round 17
// speedup vs baseline: 1.2965x; 1.0022x over previous
#include <cuda_runtime.h>
#include <math.h>

// Shape fixed by reference: B=2, L=2048, H=16, E=64
#define B_  2
#define L_  2048
#define H_  16
#define E_  64
#define BH_ 32            // B*H chains
#define CH_ 64            // chunk length along s
#define NC_ 32            // chunks per chain
#define HE_ 1024          // H*E row stride in floats
#define NBLK (BH_ * NC_)  // 1024 blocks
#define NSUB 4            // sub-groups of 64 channels
#define RPS  16           // rows per sub

// Scratch (__device__ globals; no allocations allowed)
__device__ float g_E   [BH_ * L_];           // e-scores
__device__ float g_agg [NBLK * E_];          // per-chunk sum of e*V
__device__ float g_aggE[NBLK];               // per-chunk sum of e
__device__ float g_sub [NBLK * NSUB * E_];   // per-sub partial sums of e*V

// ---------------- K1: e-scores + per-chunk/per-sub aggregates (R8 proven) --
__global__ __launch_bounds__(256, 8) void k_aggregate(
    const float* __restrict__ keys,
    const float* __restrict__ values,
    const float* __restrict__ w_score)
{
    __shared__ float sV[CH_ * E_];     // 16 KB V tile
    __shared__ float se[CH_];
    __shared__ float spEV[NSUB * E_];
    __shared__ float spE[NSUB];

    const int tid = threadIdx.x;
    const int blk = blockIdx.x;
    const int bh  = blk >> 5;          // / NC_
    const int c   = blk & 31;          // % NC_
    const int b   = bh >> 4;
    const int h   = bh & 15;
    const int base = ((b * L_ + c * CH_) * H_ + h) * E_;

    const int d   = tid & 63;
    const int sub = tid >> 6;
    const int r0  = sub * RPS;

    // e[row] = exp(0.125 * dot(K[row], w_k)); 4 threads per row
    {
        const int row = tid >> 2, q = tid & 3;
        const float4* kq = reinterpret_cast<const float4*>(
            keys + base + row * HE_ + q * 16);
        const float4* wq = reinterpret_cast<const float4*>(
            w_score + E_ + q * 16);
        float dot = 0.f;
        #pragma unroll
        for (int j = 0; j < 4; j++) {
            const float4 k4 = kq[j];
            const float4 w4 = wq[j];
            dot += k4.x * w4.x + k4.y * w4.y + k4.z * w4.z + k4.w * w4.w;
        }
        dot += __shfl_xor_sync(0xffffffffu, dot, 1);
        dot += __shfl_xor_sync(0xffffffffu, dot, 2);
        if (q == 0) {
            const float e = __expf(dot * 0.125f);
            se[row] = e;
            g_E[bh * L_ + c * CH_ + row] = e;
        }
    }

    // stage V tile (float4, coalesced)
    {
        const float4* vg = reinterpret_cast<const float4*>(values + base);
        float4* sv4 = reinterpret_cast<float4*>(sV);
        #pragma unroll
        for (int i = 0; i < 4; i++) {
            const int idx = tid + i * 256;
            sv4[idx] = vg[(idx >> 4) * (HE_ / 4) + (idx & 15)];
        }
    }
    __syncthreads();

    // per-sub partial aggregates over 16 rows; persist per-sub EV partials
    {
        float sumE = 0.f, sumEV = 0.f;
        #pragma unroll
        for (int r = 0; r < RPS; r++) {
            const float e = se[r0 + r];
            sumE += e;
            sumEV = fmaf(e, sV[(r0 + r) * E_ + d], sumEV);
        }
        g_sub[(blk * NSUB + sub) * E_ + d] = sumEV;
        spEV[sub * E_ + d] = sumEV;
        if (d == 0) spE[sub] = sumE;
    }
    __syncthreads();

    if (tid < E_) {
        g_agg[blk * E_ + tid] =
            spEV[tid] + spEV[E_ + tid] + spEV[2 * E_ + tid] + spEV[3 * E_ + tid];
        if (tid == 0)
            g_aggE[blk] = spE[0] + spE[1] + spE[2] + spE[3];
    }

#if __CUDA_ARCH__ >= 900
    cudaTriggerProgrammaticLaunchCompletion();
#endif
}

// ---------------- K2: PDL secondary — unrolled predicated prefix loads -----
__global__ __launch_bounds__(256, 8) void k_output(
    const float* __restrict__ values,
    float* __restrict__ out)
{
    __shared__ float sV[CH_ * E_];     // 16 KB V tile (prologue-staged)
    __shared__ float se[CH_];          // e-scores for this chunk
    __shared__ float srcp[CH_];        // 1 / cumulative-E per row
    __shared__ float sqEV[NSUB * E_];  // chunk-prefix partials

    const int tid = threadIdx.x;
    const int blk = blockIdx.x;
    const int bh  = blk >> 5;
    const int c   = blk & 31;
    const int b   = bh >> 4;
    const int h   = bh & 15;
    const int base = ((b * L_ + c * CH_) * H_ + h) * E_;

    const int d   = tid & 63;
    const int sub = tid >> 6;
    const int r0  = sub * RPS;

    // ---- prologue (independent of K1): stage V tile into smem
    {
        const float4* vg = reinterpret_cast<const float4*>(values + base);
        float4* sv4 = reinterpret_cast<float4*>(sV);
        #pragma unroll
        for (int i = 0; i < 4; i++) {
            const int idx = tid + i * 256;
            sv4[idx] = vg[(idx >> 4) * (HE_ / 4) + (idx & 15)];
        }
    }

#if __CUDA_ARCH__ >= 900
    cudaGridDependencySynchronize();
#endif

    // ---- chunk-prefix EV loads: COMPILE-TIME 8 iterations, predicated.
    // All (<=8) L2 loads issue independently -> one exposed latency, not 8.
    {
        float pEV = 0.f;
        #pragma unroll
        for (int k = 0; k < 8; k++) {
            const int t = sub + k * NSUB;
            float v = 0.f;
            if (t < c) v = g_agg[(bh * NC_ + t) * E_ + d];
            pEV += v;
        }
        sqEV[sub * E_ + d] = pEV;
    }

    // ---- warp 7: E-side. preE reduce + pair-scan + reciprocals (2 MUFU)
    if (tid >= 224) {
        const int lane = tid & 31;
        float pe = (lane < c) ? g_aggE[bh * NC_ + lane] : 0.f;
        #pragma unroll
        for (int o = 16; o; o >>= 1) pe += __shfl_xor_sync(0xffffffffu, pe, o);
        const float2 e2 = reinterpret_cast<const float2*>(
            g_E + bh * L_ + c * CH_)[lane];
        const float p = e2.x + e2.y;
        float incl = p;
        #pragma unroll
        for (int o = 1; o < 32; o <<= 1) {
            const float t = __shfl_up_sync(0xffffffffu, incl, o);
            if (lane >= o) incl += t;
        }
        const float excl = incl - p;
        se[2 * lane]     = e2.x;
        se[2 * lane + 1] = e2.y;
        srcp[2 * lane]     = __fdividef(1.f, pe + excl + e2.x);
        srcp[2 * lane + 1] = __fdividef(1.f, pe + incl);
    }
    __syncthreads();

    // ---- exclusive EV start for this thread
    float accEV = sqEV[d] + sqEV[E_ + d] + sqEV[2 * E_ + d] + sqEV[3 * E_ + d];
    #pragma unroll
    for (int s = 0; s < NSUB - 1; s++)
        if (s < sub) accEV += g_sub[(blk * NSUB + s) * E_ + d];

    // ---- inclusive scan over 16 rows, V from smem, divide-free output
    float* o = out + base + r0 * HE_ + d;
    #pragma unroll
    for (int r = 0; r < RPS; r++) {
        accEV = fmaf(se[r0 + r], sV[(r0 + r) * E_ + d], accEV);
        o[r * HE_] = accEV * srcp[r0 + r];
    }
}

extern "C" void kernel_launch(void* const* d_in, const int* in_sizes, int n_in,
                              void* d_out, int out_size) {
    // inputs: 0=queries (unused: a_q cancels in softmax), 1=keys, 2=values,
    //         3=w_score, 4=b_score (unused: cancels)
    const float* keys   = (const float*)d_in[1];
    const float* values = (const float*)d_in[2];
    const float* w      = (const float*)d_in[3];
    float* out = (float*)d_out;

    k_aggregate<<<NBLK, 256>>>(keys, values, w);

    cudaLaunchConfig_t cfg = {};
    cfg.gridDim = dim3(NBLK, 1, 1);
    cfg.blockDim = dim3(256, 1, 1);
    cfg.dynamicSmemBytes = 0;
    cfg.stream = 0;
    cudaLaunchAttribute attr[1];
    attr[0].id = cudaLaunchAttributeProgrammaticStreamSerialization;
    attr[0].val.programmaticStreamSerializationAllowed = 1;
    cfg.attrs = attr;
    cfg.numAttrs = 1;
    cudaLaunchKernelEx(&cfg, k_output, values, out);
}